// round 2
// baseline (speedup 1.0000x reference)
#include <cuda_runtime.h>
#include <cuda_fp16.h>
#include <math.h>
#include <stdint.h>

// ---------------- problem constants (fixed by setup_inputs) ----------------
#define NN 4096
#define LL 256
#define TLGT 128

constexpr float MUv     = 1e-3f;
constexpr float ONEMMU  = 1.0f - 1e-3f;
constexpr float NE      = 9.765625f;                    // 4*10000/4096
constexpr float INV_NM1 = 1.0f / 4095.0f;
constexpr float EPSF    = 2.2204460492503131e-16f;      // float64 eps
constexpr float CA      = 4096.0f;   // alpha storage scale
constexpr float CB      = 8.0f;      // beta  storage scale

// ---------------- scratch (device globals; fp16 state matrices) ------------
__device__ uint4 g_A[(size_t)NN * NN / 8];   // 32 MB, halves: A = CA*alpha
__device__ uint4 g_B[(size_t)NN * NN / 8];   // 32 MB, halves: B = CB*beta
__device__ float g_cs[3][NN];                // rotating colsum / denom (scaled)
__device__ int   g_cnt[2];

// ---------------- tiling: 256 threads (32x8), 256 cols x 128 rows per CTA --
constexpr int TX  = 32;
constexpr int TYD = 8;
constexpr int CPC = 256;   // columns per CTA (32 lanes * 8 halves)
constexpr int RPC = 128;   // rows per CTA
constexpr int RPT = 16;    // rows per thread

__device__ __forceinline__ float clip01(float x) {
    return fminf(fmaxf(x, 0.0f), 1.0f);
}

// ---------------- popcount of two h rows ----------------
__global__ void k_popcnt(const int* __restrict__ h) {
    int row = blockIdx.x ? (LL - 1) : 0;
    const int* hr = h + (size_t)row * NN;
    int t = threadIdx.x;
    int s = 0;
    for (int i = t; i < NN; i += 256) s += hr[i];
    __shared__ int sm[256];
    sm[t] = s;
    __syncthreads();
    for (int st = 128; st > 0; st >>= 1) {
        if (t < st) sm[t] += sm[t + st];
        __syncthreads();
    }
    if (t == 0) g_cnt[blockIdx.x] = sm[0];
}

// analytic scaled colsum/denom of the binary-emission initial matrix
__global__ void k_init_cs(const int* __restrict__ h, int row, int cntIdx,
                          int dstIdx, int zeroIdx, float scale) {
    int j = blockIdx.x * 256 + threadIdx.x;
    int hj = h[(size_t)row * NN + j];
    int c = g_cnt[cntIdx];
    int match = hj ? (c - 1) : (NN - 1 - c);
    int mism  = (NN - 1) - match;
    g_cs[dstIdx][j]  = ((float)match * ONEMMU + (float)mism * MUv) * INV_NM1 * scale;
    g_cs[zeroIdx][j] = 0.0f;
}

// A0 = CA * theta0/(N-1), diag 0 (fp16)
__global__ __launch_bounds__(256) void k_alpha0(const int* __restrict__ h) {
    __shared__ int sh[RPC];
    int tx = threadIdx.x, ty = threadIdx.y;
    int t = ty * TX + tx;
    int colbase = blockIdx.x * CPC + tx * 8;
    int i0 = blockIdx.y * RPC;
    if (t < RPC) sh[t] = h[i0 + t];
    int hj[8];
#pragma unroll
    for (int c = 0; c < 8; c++) hj[c] = h[colbase + c];
    __syncthreads();
    bool hasDiag = ((int)blockIdx.y == 2 * (int)blockIdx.x) ||
                   ((int)blockIdx.y == 2 * (int)blockIdx.x + 1);
    const float S = CA * INV_NM1;
    for (int k = 0; k < RPT; k++) {
        int i = i0 + ty + TYD * k;
        int hi = sh[ty + TYD * k];
        float x[8];
#pragma unroll
        for (int c = 0; c < 8; c++) {
            x[c] = ((hi == hj[c]) ? ONEMMU : MUv) * S;
            if (hasDiag && i == colbase + c) x[c] = 0.0f;
        }
        uint4 v; __half2* hp = (__half2*)&v;
#pragma unroll
        for (int q = 0; q < 4; q++) hp[q] = __floats2half2_rn(x[2 * q], x[2 * q + 1]);
        g_A[(size_t)i * (NN / 8) + (colbase >> 3)] = v;
    }
}

// forward step (fp16 state): A' = theta * (A*coef + addc), diag 0;
// coef = (1-r)*CA/S'_j, addc = CA*r/(N-1). Fused colsum of A' into g_cs[wr].
__global__ __launch_bounds__(256) void k_fwd(const int* __restrict__ h,
                                             const float* __restrict__ m,
                                             int l, int rd, int wr, int zr) {
    __shared__ int sh[RPC];
    __shared__ float red[TYD][TX][8];
    int tx = threadIdx.x, ty = threadIdx.y;
    int t = ty * TX + tx;
    int colbase = blockIdx.x * CPC + tx * 8;
    int i0 = blockIdx.y * RPC;
    const int* hr = h + (size_t)l * NN;
    if (t < RPC) sh[t] = hr[i0 + t];
    int hj[8];
#pragma unroll
    for (int c = 0; c < 8; c++) hj[c] = hr[colbase + c];
    if (ty == 0 && blockIdx.y == 0) {
#pragma unroll
        for (int c = 0; c < 8; c++) g_cs[zr][colbase + c] = 0.0f;
    }
    float r = -expm1f(-NE * m[l - 1]);
    float addc = r * (CA * INV_NM1);
    float oneMr = 1.0f - r;
    float coef[8];
#pragma unroll
    for (int c = 0; c < 8; c++) coef[c] = oneMr * CA / g_cs[rd][colbase + c];
    __syncthreads();
    bool hasDiag = ((int)blockIdx.y == 2 * (int)blockIdx.x) ||
                   ((int)blockIdx.y == 2 * (int)blockIdx.x + 1);
    float acc[8];
#pragma unroll
    for (int c = 0; c < 8; c++) acc[c] = 0.0f;
    uint4* Ap = g_A + (size_t)i0 * (NN / 8) + (colbase >> 3);
#pragma unroll 4
    for (int k = 0; k < RPT; k++) {
        int i = i0 + ty + TYD * k;
        int hi = sh[ty + TYD * k];
        uint4 av = Ap[(size_t)(ty + TYD * k) * (NN / 8)];
        __half2* ah = (__half2*)&av;
        float f[8];
#pragma unroll
        for (int q = 0; q < 4; q++) {
            float2 fq = __half22float2(ah[q]);
            f[2 * q] = fq.x; f[2 * q + 1] = fq.y;
        }
        float x[8];
#pragma unroll
        for (int c = 0; c < 8; c++) {
            float th = (hi == hj[c]) ? ONEMMU : MUv;
            x[c] = th * fmaf(f[c], coef[c], addc);
            if (hasDiag && i == colbase + c) x[c] = 0.0f;
            acc[c] += x[c];
        }
        uint4 ov; __half2* oh = (__half2*)&ov;
#pragma unroll
        for (int q = 0; q < 4; q++) oh[q] = __floats2half2_rn(x[2 * q], x[2 * q + 1]);
        Ap[(size_t)(ty + TYD * k) * (NN / 8)] = ov;
    }
#pragma unroll
    for (int c = 0; c < 8; c++) red[ty][tx][c] = acc[c];
    __syncthreads();
    if (ty == 0) {
#pragma unroll
        for (int c = 0; c < 8; c++) {
            float s = 0.0f;
#pragma unroll
            for (int q = 0; q < TYD; q++) s += red[q][tx][c];
            atomicAdd(&g_cs[wr][colbase + c], s);
        }
    }
}

// backward step (fp16 state): x = (1-r)*CB*theta1*Bprev/denom' + CB*r, diag 0;
// fused next-denom acc = sum theta0 * x / (N-1).
__global__ __launch_bounds__(256) void k_bwd(const int* __restrict__ h,
                                             const float* __restrict__ m,
                                             int l, int first,
                                             int rd, int wr, int zr) {
    __shared__ int sh1[RPC], sh0[RPC];
    __shared__ float red[TYD][TX][8];
    int tx = threadIdx.x, ty = threadIdx.y;
    int t = ty * TX + tx;
    int colbase = blockIdx.x * CPC + tx * 8;
    int i0 = blockIdx.y * RPC;
    const int* hr1 = h + (size_t)(l + 1) * NN;
    const int* hr0 = h + (size_t)l * NN;
    if (t < RPC) { sh1[t] = hr1[i0 + t]; sh0[t] = hr0[i0 + t]; }
    int hj1[8], hj0[8];
#pragma unroll
    for (int c = 0; c < 8; c++) { hj1[c] = hr1[colbase + c]; hj0[c] = hr0[colbase + c]; }
    if (ty == 0 && blockIdx.y == 0) {
#pragma unroll
        for (int c = 0; c < 8; c++) g_cs[zr][colbase + c] = 0.0f;
    }
    float r = -expm1f(-NE * m[l]);
    float addc = CB * r;
    float oneMr = 1.0f - r;
    float coef[8];
#pragma unroll
    for (int c = 0; c < 8; c++) coef[c] = oneMr * CB / g_cs[rd][colbase + c];
    __syncthreads();
    bool hasDiag = ((int)blockIdx.y == 2 * (int)blockIdx.x) ||
                   ((int)blockIdx.y == 2 * (int)blockIdx.x + 1);
    float acc[8];
#pragma unroll
    for (int c = 0; c < 8; c++) acc[c] = 0.0f;
    uint4* Bp = g_B + (size_t)i0 * (NN / 8) + (colbase >> 3);
#pragma unroll 4
    for (int k = 0; k < RPT; k++) {
        int i = i0 + ty + TYD * k;
        int hi1 = sh1[ty + TYD * k];
        int hi0 = sh0[ty + TYD * k];
        float f[8];
        if (first) {
#pragma unroll
            for (int c = 0; c < 8; c++) f[c] = CB;   // beta_prev == 1
        } else {
            uint4 bv = Bp[(size_t)(ty + TYD * k) * (NN / 8)];
            __half2* bh = (__half2*)&bv;
#pragma unroll
            for (int q = 0; q < 4; q++) {
                float2 fq = __half22float2(bh[q]);
                f[2 * q] = fq.x; f[2 * q + 1] = fq.y;
            }
        }
        float x[8];
#pragma unroll
        for (int c = 0; c < 8; c++) {
            float th1 = (hi1 == hj1[c]) ? ONEMMU : MUv;
            x[c] = fmaf(th1 * f[c], coef[c], addc);
            if (hasDiag && i == colbase + c) x[c] = 0.0f;
            float th0 = (hi0 == hj0[c]) ? ONEMMU : MUv;
            acc[c] = fmaf(th0, x[c], acc[c]);
        }
        uint4 ov; __half2* oh = (__half2*)&ov;
#pragma unroll
        for (int q = 0; q < 4; q++) oh[q] = __floats2half2_rn(x[2 * q], x[2 * q + 1]);
        Bp[(size_t)(ty + TYD * k) * (NN / 8)] = ov;
    }
#pragma unroll
    for (int c = 0; c < 8; c++) red[ty][tx][c] = acc[c];
    __syncthreads();
    if (ty == 0) {
#pragma unroll
        for (int c = 0; c < 8; c++) {
            float s = 0.0f;
#pragma unroll
            for (int q = 0; q < TYD; q++) s += red[q][tx][c];
            atomicAdd(&g_cs[wr][colbase + c], s * INV_NM1);
        }
    }
}

// psum[j] = sum_i clip01(A/CA)*clip01(B/CB)  into g_cs[2]
__global__ __launch_bounds__(256) void k_psum() {
    __shared__ float red[TYD][TX][8];
    int tx = threadIdx.x, ty = threadIdx.y;
    int colbase = blockIdx.x * CPC + tx * 8;
    int i0 = blockIdx.y * RPC;
    float acc[8];
#pragma unroll
    for (int c = 0; c < 8; c++) acc[c] = 0.0f;
    const uint4* Ap = g_A + (size_t)i0 * (NN / 8) + (colbase >> 3);
    const uint4* Bp = g_B + (size_t)i0 * (NN / 8) + (colbase >> 3);
#pragma unroll 4
    for (int k = 0; k < RPT; k++) {
        uint4 av = Ap[(size_t)(ty + TYD * k) * (NN / 8)];
        uint4 bv = Bp[(size_t)(ty + TYD * k) * (NN / 8)];
        __half2* ah = (__half2*)&av;
        __half2* bh = (__half2*)&bv;
#pragma unroll
        for (int q = 0; q < 4; q++) {
            float2 fa = __half22float2(ah[q]);
            float2 fb = __half22float2(bh[q]);
            acc[2 * q]     += clip01(fa.x * (1.0f / CA)) * clip01(fb.x * (1.0f / CB));
            acc[2 * q + 1] += clip01(fa.y * (1.0f / CA)) * clip01(fb.y * (1.0f / CB));
        }
    }
#pragma unroll
    for (int c = 0; c < 8; c++) red[ty][tx][c] = acc[c];
    __syncthreads();
    if (ty == 0) {
#pragma unroll
        for (int c = 0; c < 8; c++) {
            float s = 0.0f;
#pragma unroll
            for (int q = 0; q < TYD; q++) s += red[q][tx][c];
            atomicAdd(&g_cs[2][colbase + c], s);
        }
    }
}

// p = clip(a)*clip(b)/psum -> out[0..N^2); alpha -> out[2N^2..); beta -> out[3N^2..)
__global__ __launch_bounds__(256) void k_post(float* __restrict__ out, size_t osz) {
    int tx = threadIdx.x, ty = threadIdx.y;
    int colbase = blockIdx.x * CPC + tx * 8;
    int i0 = blockIdx.y * RPC;
    float psinv[8];
#pragma unroll
    for (int c = 0; c < 8; c++) psinv[c] = 1.0f / g_cs[2][colbase + c];
    const size_t NSQ = (size_t)NN * NN;
    const uint4* Ap = g_A + (size_t)i0 * (NN / 8) + (colbase >> 3);
    const uint4* Bp = g_B + (size_t)i0 * (NN / 8) + (colbase >> 3);
    for (int k = 0; k < RPT; k++) {
        int i = i0 + ty + TYD * k;
        uint4 av = Ap[(size_t)(ty + TYD * k) * (NN / 8)];
        uint4 bv = Bp[(size_t)(ty + TYD * k) * (NN / 8)];
        __half2* ah = (__half2*)&av;
        __half2* bh = (__half2*)&bv;
        float a[8], b[8], p[8];
#pragma unroll
        for (int q = 0; q < 4; q++) {
            float2 fa = __half22float2(ah[q]);
            float2 fb = __half22float2(bh[q]);
            a[2 * q] = fa.x * (1.0f / CA); a[2 * q + 1] = fa.y * (1.0f / CA);
            b[2 * q] = fb.x * (1.0f / CB); b[2 * q + 1] = fb.y * (1.0f / CB);
        }
#pragma unroll
        for (int c = 0; c < 8; c++) p[c] = clip01(a[c]) * clip01(b[c]) * psinv[c];
        size_t o = (size_t)i * NN + colbase;
        float4* po = (float4*)(out + o);
        float4* ao = (float4*)(out + 2 * NSQ + o);
        float4* bo = (float4*)(out + 3 * NSQ + o);
        if (o + 8 <= osz) {
            po[0] = make_float4(p[0], p[1], p[2], p[3]);
            po[1] = make_float4(p[4], p[5], p[6], p[7]);
        }
        if (2 * NSQ + o + 8 <= osz) {
            ao[0] = make_float4(a[0], a[1], a[2], a[3]);
            ao[1] = make_float4(a[4], a[5], a[6], a[7]);
        }
        if (3 * NSQ + o + 8 <= osz) {
            bo[0] = make_float4(b[0], b[1], b[2], b[3]);
            bo[1] = make_float4(b[4], b[5], b[6], b[7]);
        }
    }
}

// d[i,j] = -0.5*(log pc[i,j] + log pc[j,i]) * offdiag
__global__ void k_dist(const float* __restrict__ p, float* __restrict__ d,
                       size_t dmax) {
    __shared__ float tp[32][33];
    int tx = threadIdx.x, ty = threadIdx.y;    // 32 x 8
    int bi = blockIdx.y, bj = blockIdx.x;
#pragma unroll
    for (int k = 0; k < 4; k++) {
        int r = bj * 32 + ty + 8 * k;
        int c = bi * 32 + tx;
        tp[ty + 8 * k][tx] = logf(fmaxf(p[(size_t)r * NN + c], EPSF));
    }
    __syncthreads();
#pragma unroll
    for (int k = 0; k < 4; k++) {
        int i = bi * 32 + ty + 8 * k;
        int j = bj * 32 + tx;
        float lp  = logf(fmaxf(p[(size_t)i * NN + j], EPSF));
        float lpt = tp[tx][ty + 8 * k];
        float v = (i == j) ? 0.0f : -0.5f * (lp + lpt);
        size_t o = (size_t)i * NN + j;
        if (o < dmax) d[o] = v;
    }
}

// ---------------- launcher ----------------
extern "C" void kernel_launch(void* const* d_in, const int* in_sizes, int n_in,
                              void* d_out, int out_size) {
    const int*   h = (const int*)d_in[0];
    const float* m = (const float*)d_in[1];
    float* out = (float*)d_out;
    size_t osz = (size_t)out_size;
    const size_t NSQ = (size_t)NN * NN;

    dim3 blk(TX, TYD);
    dim3 grid(NN / CPC, NN / RPC);   // 16 x 32 = 512 CTAs

    // ---- forward ----
    k_popcnt<<<2, 256>>>(h);
    k_init_cs<<<NN / 256, 256>>>(h, 0, 0, /*dst=*/1, /*zero=*/2, CA);
    k_alpha0<<<grid, blk>>>(h);
    for (int l = 1; l <= TLGT; l++) {
        k_fwd<<<grid, blk>>>(h, m, l, l % 3, (l + 1) % 3, (l + 2) % 3);
    }

    // ---- backward ----
    k_init_cs<<<NN / 256, 256>>>(h, LL - 1, 1, /*dst=*/0, /*zero=*/1, CB);
    const int nb = LL - 1 - TLGT;   // 127 steps
    for (int t = 0; t < nb; t++) {
        int l = LL - 2 - t;
        k_bwd<<<grid, blk>>>(h, m, l, (t == 0) ? 1 : 0,
                             t % 3, (t + 1) % 3, (t + 2) % 3);
    }

    // ---- posterior + distance ----
    k_psum<<<grid, blk>>>();   // g_cs[2] zeroed by last bwd step's zero-duty
    k_post<<<grid, blk>>>(out, osz);
    if (osz > NSQ) {
        k_dist<<<dim3(NN / 32, NN / 32), dim3(32, 8)>>>(out, out + NSQ,
                                                        osz - NSQ);
    }
}